// round 2
// baseline (speedup 1.0000x reference)
#include <cuda_runtime.h>
#include <cstdint>

#define BATCH 2
#define SEQ   1024
#define HS    768
#define NH    12
#define HD    64
#define WIN   64
#define HALF  32
#define MTOK  (BATCH*SEQ)   // 2048

#define BM 128
#define BN 128
#define BK 16
#define NKT (HS / BK)       // 48

// Scratch (device globals: no allocation allowed)
__device__ float g_q[MTOK*HS];
__device__ float g_k[MTOK*HS];
__device__ float g_v[MTOK*HS];
__device__ float g_ctx[MTOK*HS];

// ---------------------------------------------------------------------------
// tf32 helpers
// ---------------------------------------------------------------------------
__device__ __forceinline__ void split_tf32(float x, uint32_t& hi, uint32_t& lo) {
    uint32_t h;
    asm("cvt.rna.tf32.f32 %0, %1;" : "=r"(h) : "f"(x));
    float hf = __uint_as_float(h);
    float r = x - hf;
    uint32_t l;
    asm("cvt.rna.tf32.f32 %0, %1;" : "=r"(l) : "f"(r));
    hi = h; lo = l;
}

__device__ __forceinline__ void mma_tf32(float* d, const uint32_t* a, const uint32_t* b) {
    asm volatile(
        "mma.sync.aligned.m16n8k8.row.col.f32.tf32.tf32.f32 "
        "{%0,%1,%2,%3}, {%4,%5,%6,%7}, {%8,%9}, {%0,%1,%2,%3};"
        : "+f"(d[0]), "+f"(d[1]), "+f"(d[2]), "+f"(d[3])
        : "r"(a[0]), "r"(a[1]), "r"(a[2]), "r"(a[3]), "r"(b[0]), "r"(b[1]));
}

__device__ __forceinline__ void cp16(void* dst_smem, const void* src) {
    uint32_t d = (uint32_t)__cvta_generic_to_shared(dst_smem);
    asm volatile("cp.async.cg.shared.global [%0], [%1], 16;" :: "r"(d), "l"(src));
}
#define CP_COMMIT() asm volatile("cp.async.commit_group;")
#define CP_WAIT0()  asm volatile("cp.async.wait_group 0;")

// ---------------------------------------------------------------------------
// 128x128 tf32x3 GEMM: C[M,N] = A[M,K] @ W[N,K]^T + bias.  K = HS = 768.
// 256 threads = 8 warps (2 M x 4 N), warp tile 64x32, mma m16n8k8.
// smem [row][20] padding: conflict-free fragment loads AND 16B cp.async.
// ---------------------------------------------------------------------------
__device__ __forceinline__ void gemm_tf32x3(
    const float* __restrict__ A, const float* __restrict__ W,
    const float* __restrict__ bias, float* __restrict__ C,
    int bx, int by)
{
    __shared__ float As[2][BM][20];
    __shared__ float Bs[2][BN][20];

    const int tid  = threadIdx.x;
    const int lane = tid & 31;
    const int warp = tid >> 5;
    const int wm   = warp & 1;      // 0..1
    const int wn   = warp >> 1;     // 0..3
    const int g    = lane >> 2;     // 0..7
    const int tg   = lane & 3;      // 0..3

    const int lrow = tid >> 1;          // 0..127
    const int lc0  = (tid & 1) * 8;     // 0 or 8 (floats)
    const float* Abase = A + (size_t)(by * BM + lrow) * HS + lc0;
    const float* Bbase = W + (size_t)(bx * BN + lrow) * HS + lc0;

    float acc[4][4][4];
    #pragma unroll
    for (int i = 0; i < 4; i++)
        #pragma unroll
        for (int j = 0; j < 4; j++)
            #pragma unroll
            for (int r = 0; r < 4; r++) acc[i][j][r] = 0.f;

    // stage 0
    {
        cp16(&As[0][lrow][lc0],     Abase);
        cp16(&As[0][lrow][lc0 + 4], Abase + 4);
        cp16(&Bs[0][lrow][lc0],     Bbase);
        cp16(&Bs[0][lrow][lc0 + 4], Bbase + 4);
        CP_COMMIT();
    }
    CP_WAIT0();
    __syncthreads();

    for (int kt = 0; kt < NKT; kt++) {
        const int cur = kt & 1;
        if (kt + 1 < NKT) {
            const int nxt = cur ^ 1;
            const int ko = (kt + 1) * BK;
            cp16(&As[nxt][lrow][lc0],     Abase + ko);
            cp16(&As[nxt][lrow][lc0 + 4], Abase + ko + 4);
            cp16(&Bs[nxt][lrow][lc0],     Bbase + ko);
            cp16(&Bs[nxt][lrow][lc0 + 4], Bbase + ko + 4);
            CP_COMMIT();
        }

        #pragma unroll
        for (int ks = 0; ks < BK; ks += 8) {
            uint32_t ahi[4][4], alo[4][4], bhi[4][2], blo[4][2];
            #pragma unroll
            for (int i = 0; i < 4; i++) {
                const int r0 = wm * 64 + i * 16 + g;
                split_tf32(As[cur][r0][ks + tg],         ahi[i][0], alo[i][0]);
                split_tf32(As[cur][r0 + 8][ks + tg],     ahi[i][1], alo[i][1]);
                split_tf32(As[cur][r0][ks + tg + 4],     ahi[i][2], alo[i][2]);
                split_tf32(As[cur][r0 + 8][ks + tg + 4], ahi[i][3], alo[i][3]);
            }
            #pragma unroll
            for (int j = 0; j < 4; j++) {
                const int n0 = wn * 32 + j * 8 + g;
                split_tf32(Bs[cur][n0][ks + tg],     bhi[j][0], blo[j][0]);
                split_tf32(Bs[cur][n0][ks + tg + 4], bhi[j][1], blo[j][1]);
            }
            // three passes: long dependency distance per accumulator tile
            #pragma unroll
            for (int i = 0; i < 4; i++)
                #pragma unroll
                for (int j = 0; j < 4; j++) mma_tf32(acc[i][j], ahi[i], bhi[j]);
            #pragma unroll
            for (int i = 0; i < 4; i++)
                #pragma unroll
                for (int j = 0; j < 4; j++) mma_tf32(acc[i][j], ahi[i], blo[j]);
            #pragma unroll
            for (int i = 0; i < 4; i++)
                #pragma unroll
                for (int j = 0; j < 4; j++) mma_tf32(acc[i][j], alo[i], bhi[j]);
        }

        if (kt + 1 < NKT) CP_WAIT0();
        __syncthreads();
    }

    // epilogue
    #pragma unroll
    for (int i = 0; i < 4; i++) {
        const int row = by * BM + wm * 64 + i * 16 + g;
        #pragma unroll
        for (int j = 0; j < 4; j++) {
            const int col = bx * BN + wn * 32 + j * 8 + tg * 2;
            const float b0 = bias[col], b1 = bias[col + 1];
            float2 v0 = make_float2(acc[i][j][0] + b0, acc[i][j][1] + b1);
            float2 v1 = make_float2(acc[i][j][2] + b0, acc[i][j][3] + b1);
            *(float2*)&C[(size_t)row * HS + col]       = v0;
            *(float2*)&C[(size_t)(row + 8) * HS + col] = v1;
        }
    }
}

__global__ __launch_bounds__(256, 1) void qkv_kernel(
    const float* __restrict__ X,
    const float* __restrict__ Wq, const float* __restrict__ bq,
    const float* __restrict__ Wk, const float* __restrict__ bk,
    const float* __restrict__ Wv, const float* __restrict__ bv)
{
    const float* W; const float* b; float* C;
    if (blockIdx.z == 0)      { W = Wq; b = bq; C = g_q; }
    else if (blockIdx.z == 1) { W = Wk; b = bk; C = g_k; }
    else                      { W = Wv; b = bv; C = g_v; }
    gemm_tf32x3(X, W, b, C, blockIdx.x, blockIdx.y);
}

__global__ __launch_bounds__(256, 1) void out_kernel(
    const float* __restrict__ Wo, const float* __restrict__ bo,
    float* __restrict__ out)
{
    gemm_tf32x3(g_ctx, Wo, bo, out, blockIdx.x, blockIdx.y);
}

// ---------------------------------------------------------------------------
// Sliding-window attention. Block = 16 queries of one (batch, head).
// One warp per query. Exact zero-padding semantics (OOB score = 0, v = 0).
// ---------------------------------------------------------------------------
__global__ __launch_bounds__(512) void attn_kernel()
{
    __shared__ float Ks[79][65];   // keys s0-32 .. s0+46, stride 65 (conflict-free)
    __shared__ float Vs[79][65];
    __shared__ float Ps[16][64];

    const int s0 = blockIdx.x * 16;
    const int h  = blockIdx.y;
    const int b  = blockIdx.z;
    const int tid = threadIdx.x;
    const int base = (b * SEQ) * HS + h * HD;

    for (int i = tid; i < 79 * 64; i += 512) {
        int r = i >> 6, d = i & 63;
        int j = s0 - HALF + r;
        float kv = 0.f, vv = 0.f;
        if (j >= 0 && j < SEQ) {
            int off = base + j * HS + d;
            kv = g_k[off];
            vv = g_v[off];
        }
        Ks[r][d] = kv;
        Vs[r][d] = vv;
    }
    __syncthreads();

    const int wq   = tid >> 5;
    const int lane = tid & 31;
    const float* qrow = g_q + base + (s0 + wq) * HS;

    float sc0 = 0.f, sc1 = 0.f;
    #pragma unroll
    for (int d = 0; d < 64; d++) {
        float qd = __ldg(qrow + d);            // L1 broadcast
        sc0 += qd * Ks[wq + lane][d];
        sc1 += qd * Ks[wq + lane + 32][d];
    }
    sc0 *= 0.125f;
    sc1 *= 0.125f;

    float m = fmaxf(sc0, sc1);
    #pragma unroll
    for (int o = 16; o; o >>= 1) m = fmaxf(m, __shfl_xor_sync(0xFFFFFFFFu, m, o));
    float e0 = __expf(sc0 - m);
    float e1 = __expf(sc1 - m);
    float sum = e0 + e1;
    #pragma unroll
    for (int o = 16; o; o >>= 1) sum += __shfl_xor_sync(0xFFFFFFFFu, sum, o);
    float inv = 1.f / sum;
    Ps[wq][lane]      = e0 * inv;
    Ps[wq][lane + 32] = e1 * inv;
    __syncwarp();

    float c0 = 0.f, c1 = 0.f;
    #pragma unroll
    for (int w = 0; w < 64; w++) {
        float p = Ps[wq][w];
        c0 += p * Vs[wq + w][lane];
        c1 += p * Vs[wq + w][lane + 32];
    }
    int orow = base + (s0 + wq) * HS;
    g_ctx[orow + lane]      = c0;
    g_ctx[orow + lane + 32] = c1;
}

// ---------------------------------------------------------------------------
extern "C" void kernel_launch(void* const* d_in, const int* in_sizes, int n_in,
                              void* d_out, int out_size)
{
    const float* X  = (const float*)d_in[0];
    const float* Wq = (const float*)d_in[1];
    const float* bq = (const float*)d_in[2];
    const float* Wk = (const float*)d_in[3];
    const float* bk = (const float*)d_in[4];
    const float* Wv = (const float*)d_in[5];
    const float* bv = (const float*)d_in[6];
    const float* Wo = (const float*)d_in[7];
    const float* bo = (const float*)d_in[8];
    float* out = (float*)d_out;

    dim3 gemm_grid(HS / BN, MTOK / BM, 3);     // (6, 16, 3)
    qkv_kernel<<<gemm_grid, 256>>>(X, Wq, bq, Wk, bk, Wv, bv);

    dim3 attn_grid(SEQ / 16, NH, BATCH);       // (64, 12, 2)
    attn_kernel<<<attn_grid, 512>>>();

    dim3 out_grid(HS / BN, MTOK / BM, 1);      // (6, 16)
    out_kernel<<<out_grid, 256>>>(Wo, bo, out);
}

// round 4
// speedup vs baseline: 2.3275x; 2.3275x over previous
#include <cuda_runtime.h>
#include <cuda_bf16.h>
#include <cstdint>

#define BATCH 2
#define SEQ   1024
#define HS    768
#define NH    12
#define HD    64
#define WIN   64
#define HALF  32
#define MTOK  (BATCH*SEQ)   // 2048

#define BM 128
#define BN 64
#define BK 32
#define NKC (HS / BK)       // 24

// ---------------------------------------------------------------------------
// Device-global scratch (no allocation allowed)
// ---------------------------------------------------------------------------
__device__ float g_q[MTOK*HS];
__device__ float g_k[MTOK*HS];
__device__ float g_v[MTOK*HS];
__device__ __nv_bfloat16 g_xhi[MTOK*HS], g_xlo[MTOK*HS];
__device__ __nv_bfloat16 g_chi[MTOK*HS], g_clo[MTOK*HS];
__device__ __nv_bfloat16 g_wqhi[HS*HS], g_wqlo[HS*HS];
__device__ __nv_bfloat16 g_wkhi[HS*HS], g_wklo[HS*HS];
__device__ __nv_bfloat16 g_wvhi[HS*HS], g_wvlo[HS*HS];
__device__ __nv_bfloat16 g_wohi[HS*HS], g_wolo[HS*HS];

// ---------------------------------------------------------------------------
// PTX helpers
// ---------------------------------------------------------------------------
__device__ __forceinline__ uint32_t smem_u32(const void* p) {
    uint32_t a;
    asm("{ .reg .u64 t; cvta.to.shared.u64 t, %1; cvt.u32.u64 %0, t; }" : "=r"(a) : "l"(p));
    return a;
}
__device__ __forceinline__ void cp16(uint32_t dst, const void* src) {
    asm volatile("cp.async.cg.shared.global [%0], [%1], 16;" :: "r"(dst), "l"(src));
}
#define CP_COMMIT() asm volatile("cp.async.commit_group;")
#define CP_WAIT0()  asm volatile("cp.async.wait_group 0;")
#define CP_WAIT1()  asm volatile("cp.async.wait_group 1;")

__device__ __forceinline__ void ldsm4(uint32_t* r, uint32_t addr) {
    asm volatile("ldmatrix.sync.aligned.m8n8.x4.shared.b16 {%0,%1,%2,%3}, [%4];"
        : "=r"(r[0]), "=r"(r[1]), "=r"(r[2]), "=r"(r[3]) : "r"(addr));
}
__device__ __forceinline__ void mma_bf16(float* d, const uint32_t* a, uint32_t b0, uint32_t b1) {
    asm volatile(
        "mma.sync.aligned.m16n8k16.row.col.f32.bf16.bf16.f32 "
        "{%0,%1,%2,%3}, {%4,%5,%6,%7}, {%8,%9}, {%0,%1,%2,%3};"
        : "+f"(d[0]), "+f"(d[1]), "+f"(d[2]), "+f"(d[3])
        : "r"(a[0]), "r"(a[1]), "r"(a[2]), "r"(a[3]), "r"(b0), "r"(b1));
}

// ---------------------------------------------------------------------------
// smem layout per stage (bytes). Row = 32 bf16 = 64B data, padded to 80B
// (conflict-free for ldmatrix: 8-row period covers all 32 banks).
//   Ahi: [0,10240)  Alo: [10240,20480)  Bhi: [20480,25600)  Blo: [25600,30720)
// ---------------------------------------------------------------------------
#define STAGE_B  30720
#define SMEM_GEMM (2 * STAGE_B)

__device__ __forceinline__ void load_chunk(
    uint32_t sb, int st, int kc,
    const __nv_bfloat16* __restrict__ Ahi, const __nv_bfloat16* __restrict__ Alo,
    const __nv_bfloat16* __restrict__ Bhi, const __nv_bfloat16* __restrict__ Blo,
    int by, int bx, int tid)
{
    const int k0 = kc * BK;
    const uint32_t base = sb + (uint32_t)st * STAGE_B;
    #pragma unroll
    for (int it = 0; it < 6; it++) {
        int idx = it * 256 + tid;          // 0..1535
        int r  = idx >> 2;                 // 0..383
        int cb = idx & 3;                  // 16B chunk within 64B row
        const __nv_bfloat16* src; uint32_t toff; int row;
        if (r < 128)      { src = Ahi + (size_t)(by * BM + r) * HS;         toff = 0;     row = r; }
        else if (r < 256) { src = Alo + (size_t)(by * BM + (r - 128)) * HS; toff = 10240; row = r - 128; }
        else if (r < 320) { src = Bhi + (size_t)(bx * BN + (r - 256)) * HS; toff = 20480; row = r - 256; }
        else              { src = Blo + (size_t)(bx * BN + (r - 320)) * HS; toff = 25600; row = r - 320; }
        cp16(base + toff + (uint32_t)row * 80 + (uint32_t)cb * 16, src + k0 + cb * 8);
    }
}

// ---------------------------------------------------------------------------
// bf16x3 HMMA GEMM: C[M,N] = (Ahi+Alo)[M,K] @ (Bhi+Blo)[N,K]^T + bias
// CTA 128x64, 8 warps (2M x 4N), warp tile 64x16.
// ---------------------------------------------------------------------------
__device__ __forceinline__ void hgemm(
    const __nv_bfloat16* __restrict__ Ahi, const __nv_bfloat16* __restrict__ Alo,
    const __nv_bfloat16* __restrict__ Bhi, const __nv_bfloat16* __restrict__ Blo,
    const float* __restrict__ bias, float* __restrict__ C,
    int bx, int by)
{
    extern __shared__ char smem[];
    const uint32_t sb = smem_u32(smem);
    const int tid  = threadIdx.x;
    const int lane = tid & 31;
    const int warp = tid >> 5;
    const int wm   = warp & 1;          // M half
    const int wn   = warp >> 1;         // 0..3 -> N*16

    float acc[4][2][4];
    #pragma unroll
    for (int i = 0; i < 4; i++)
        #pragma unroll
        for (int j = 0; j < 2; j++)
            #pragma unroll
            for (int r = 0; r < 4; r++) acc[i][j][r] = 0.f;

    load_chunk(sb, 0, 0, Ahi, Alo, Bhi, Blo, by, bx, tid); CP_COMMIT();
    load_chunk(sb, 1, 1, Ahi, Alo, Bhi, Blo, by, bx, tid); CP_COMMIT();

    const uint32_t arow = (uint32_t)(lane & 15);
    const uint32_t asel = (uint32_t)(lane >> 4) * 16;

    for (int kc = 0; kc < NKC; kc++) {
        const int st = kc & 1;
        CP_WAIT1();
        __syncthreads();
        const uint32_t base = sb + (uint32_t)st * STAGE_B;

        #pragma unroll
        for (int ks = 0; ks < 2; ks++) {
            const uint32_t colb = (uint32_t)ks * 32 + asel;
            uint32_t ah[4][4], al[4][4], bh[4], bl[4];
            #pragma unroll
            for (int i = 0; i < 4; i++) {
                uint32_t ro = (uint32_t)(wm * 64 + i * 16) + arow;
                ldsm4(ah[i], base +         ro * 80 + colb);
                ldsm4(al[i], base + 10240 + ro * 80 + colb);
            }
            {
                uint32_t ro = (uint32_t)(wn * 16) + arow;
                ldsm4(bh, base + 20480 + ro * 80 + colb);
                ldsm4(bl, base + 25600 + ro * 80 + colb);
            }
            #pragma unroll
            for (int i = 0; i < 4; i++) {
                mma_bf16(acc[i][0], ah[i], bh[0], bh[2]);
                mma_bf16(acc[i][1], ah[i], bh[1], bh[3]);
            }
            #pragma unroll
            for (int i = 0; i < 4; i++) {
                mma_bf16(acc[i][0], ah[i], bl[0], bl[2]);
                mma_bf16(acc[i][1], ah[i], bl[1], bl[3]);
            }
            #pragma unroll
            for (int i = 0; i < 4; i++) {
                mma_bf16(acc[i][0], al[i], bh[0], bh[2]);
                mma_bf16(acc[i][1], al[i], bh[1], bh[3]);
            }
        }
        __syncthreads();
        if (kc + 2 < NKC) {
            load_chunk(sb, st, kc + 2, Ahi, Alo, Bhi, Blo, by, bx, tid);
            CP_COMMIT();
        }
    }

    const int g  = lane >> 2;
    const int tg = lane & 3;
    #pragma unroll
    for (int i = 0; i < 4; i++) {
        const int row = by * BM + wm * 64 + i * 16 + g;
        #pragma unroll
        for (int j = 0; j < 2; j++) {
            const int col = bx * BN + wn * 16 + j * 8 + tg * 2;
            const float b0 = bias[col], b1 = bias[col + 1];
            *(float2*)&C[(size_t)row * HS + col] =
                make_float2(acc[i][j][0] + b0, acc[i][j][1] + b1);
            *(float2*)&C[(size_t)(row + 8) * HS + col] =
                make_float2(acc[i][j][2] + b0, acc[i][j][3] + b1);
        }
    }
}

__global__ __launch_bounds__(256, 2) void qkv_kernel(
    const float* __restrict__ bq, const float* __restrict__ bk, const float* __restrict__ bv)
{
    const __nv_bfloat16 *Bh, *Bl; const float* b; float* C;
    if (blockIdx.z == 0)      { Bh = g_wqhi; Bl = g_wqlo; b = bq; C = g_q; }
    else if (blockIdx.z == 1) { Bh = g_wkhi; Bl = g_wklo; b = bk; C = g_k; }
    else                      { Bh = g_wvhi; Bl = g_wvlo; b = bv; C = g_v; }
    hgemm(g_xhi, g_xlo, Bh, Bl, b, C, blockIdx.x, blockIdx.y);
}

__global__ __launch_bounds__(256, 2) void out_kernel(
    const float* __restrict__ bo, float* __restrict__ out)
{
    hgemm(g_chi, g_clo, g_wohi, g_wolo, bo, out, blockIdx.x, blockIdx.y);
}

// ---------------------------------------------------------------------------
// Split fp32 -> bf16 hi/lo for X and the four weight matrices.
// ---------------------------------------------------------------------------
#define NX (MTOK*HS)
#define NW (HS*HS)

__global__ void split_kernel(
    const float* __restrict__ X,
    const float* __restrict__ Wq, const float* __restrict__ Wk,
    const float* __restrict__ Wv, const float* __restrict__ Wo)
{
    const int total = NX + 4 * NW;
    for (int i = blockIdx.x * blockDim.x + threadIdx.x; i < total; i += gridDim.x * blockDim.x) {
        const float* src; __nv_bfloat16 *hi, *lo; int r;
        if (i < NX) { src = X; hi = g_xhi; lo = g_xlo; r = i; }
        else {
            int j = i - NX; int w = j / NW; r = j - w * NW;
            if (w == 0)      { src = Wq; hi = g_wqhi; lo = g_wqlo; }
            else if (w == 1) { src = Wk; hi = g_wkhi; lo = g_wklo; }
            else if (w == 2) { src = Wv; hi = g_wvhi; lo = g_wvlo; }
            else             { src = Wo; hi = g_wohi; lo = g_wolo; }
        }
        float x = src[r];
        __nv_bfloat16 h = __float2bfloat16(x);
        hi[r] = h;
        lo[r] = __float2bfloat16(x - __bfloat162float(h));
    }
}

// ---------------------------------------------------------------------------
// Sliding-window attention, 32 queries/block, 1024 threads, one warp/query.
// K rows padded to stride 68 (16B-aligned float4, conflict-free).
// Exact zero-padding semantics (OOB score = 0, v = 0). Writes ctx bf16 hi/lo.
// ---------------------------------------------------------------------------
#define AR 95               // key rows staged: s0-32 .. s0+62
#define KST 68              // row stride in floats
#define SMEM_ATTN ((2*AR*KST + 32*64) * 4)

__global__ __launch_bounds__(1024) void attn_kernel()
{
    extern __shared__ float sm[];
    float (*Ks)[KST] = (float(*)[KST])sm;
    float (*Vs)[KST] = (float(*)[KST])(sm + AR * KST);
    float (*Ps)[64]  = (float(*)[64])(sm + 2 * AR * KST);

    const int s0 = blockIdx.x * 32;
    const int h  = blockIdx.y;
    const int b  = blockIdx.z;
    const int tid = threadIdx.x;
    const int base = (b * SEQ) * HS + h * HD;

    for (int i = tid; i < AR * 16; i += 1024) {
        int r = i >> 4, c4 = (i & 15) * 4;
        int j = s0 - HALF + r;
        float4 kv = make_float4(0.f, 0.f, 0.f, 0.f), vv = kv;
        if (j >= 0 && j < SEQ) {
            int off = base + j * HS + c4;
            kv = *(const float4*)&g_k[off];
            vv = *(const float4*)&g_v[off];
        }
        *(float4*)&Ks[r][c4] = kv;
        *(float4*)&Vs[r][c4] = vv;
    }
    __syncthreads();

    const int wq   = tid >> 5;
    const int lane = tid & 31;
    const float* qrow = g_q + base + (s0 + wq) * HS;

    float sc0 = 0.f, sc1 = 0.f;
    #pragma unroll
    for (int d4 = 0; d4 < 16; d4++) {
        float4 q  = __ldg((const float4*)(qrow + d4 * 4));
        float4 k0 = *(const float4*)&Ks[wq + lane][d4 * 4];
        float4 k1 = *(const float4*)&Ks[wq + lane + 32][d4 * 4];
        sc0 += q.x * k0.x + q.y * k0.y + q.z * k0.z + q.w * k0.w;
        sc1 += q.x * k1.x + q.y * k1.y + q.z * k1.z + q.w * k1.w;
    }
    sc0 *= 0.125f;
    sc1 *= 0.125f;

    float m = fmaxf(sc0, sc1);
    #pragma unroll
    for (int o = 16; o; o >>= 1) m = fmaxf(m, __shfl_xor_sync(0xFFFFFFFFu, m, o));
    float e0 = __expf(sc0 - m);
    float e1 = __expf(sc1 - m);
    float sum = e0 + e1;
    #pragma unroll
    for (int o = 16; o; o >>= 1) sum += __shfl_xor_sync(0xFFFFFFFFu, sum, o);
    float inv = 1.f / sum;
    Ps[wq][lane]      = e0 * inv;
    Ps[wq][lane + 32] = e1 * inv;
    __syncwarp();

    float c0 = 0.f, c1 = 0.f;
    #pragma unroll
    for (int w = 0; w < 64; w++) {
        float p = Ps[wq][w];
        float2 v = *(const float2*)&Vs[wq + w][2 * lane];
        c0 += p * v.x;
        c1 += p * v.y;
    }
    const int orow = base + (s0 + wq) * HS + 2 * lane;
    __nv_bfloat162 hi2, lo2;
    hi2.x = __float2bfloat16(c0);
    hi2.y = __float2bfloat16(c1);
    lo2.x = __float2bfloat16(c0 - __bfloat162float(hi2.x));
    lo2.y = __float2bfloat16(c1 - __bfloat162float(hi2.y));
    *(__nv_bfloat162*)&g_chi[orow] = hi2;
    *(__nv_bfloat162*)&g_clo[orow] = lo2;
}

// ---------------------------------------------------------------------------
extern "C" void kernel_launch(void* const* d_in, const int* in_sizes, int n_in,
                              void* d_out, int out_size)
{
    const float* X  = (const float*)d_in[0];
    const float* bq = (const float*)d_in[2];
    const float* bk = (const float*)d_in[4];
    const float* bv = (const float*)d_in[6];
    const float* bo = (const float*)d_in[8];
    const float* Wq = (const float*)d_in[1];
    const float* Wk = (const float*)d_in[3];
    const float* Wv = (const float*)d_in[5];
    const float* Wo = (const float*)d_in[7];
    float* out = (float*)d_out;

    static bool attr_done = false;
    if (!attr_done) {
        cudaFuncSetAttribute(qkv_kernel, cudaFuncAttributeMaxDynamicSharedMemorySize, SMEM_GEMM);
        cudaFuncSetAttribute(out_kernel, cudaFuncAttributeMaxDynamicSharedMemorySize, SMEM_GEMM);
        cudaFuncSetAttribute(attn_kernel, cudaFuncAttributeMaxDynamicSharedMemorySize, SMEM_ATTN);
        attr_done = true;
    }

    split_kernel<<<1024, 256>>>(X, Wq, Wk, Wv, Wo);

    dim3 qkv_grid(HS / BN, MTOK / BM, 3);      // (12, 16, 3)
    qkv_kernel<<<qkv_grid, 256, SMEM_GEMM>>>(bq, bk, bv);

    dim3 attn_grid(SEQ / 32, NH, BATCH);       // (32, 12, 2)
    attn_kernel<<<attn_grid, 1024, SMEM_ATTN>>>();

    dim3 out_grid(HS / BN, MTOK / BM, 1);      // (12, 16)
    out_kernel<<<out_grid, 256, SMEM_GEMM>>>(bo, out);
}